// round 1
// baseline (speedup 1.0000x reference)
#include <cuda_runtime.h>
#include <cstdint>
#include <cstddef>

#define HID     64
#define DIMH    128
#define DIMU    256
#define ROWS    32
#define NWARP   8
#define THREADS 256
#define WPAD    132   // padded row length (floats): conflict-free stride, 16B-aligned

struct Smem {
  float hs[ROWS][WPAD];        // h tile
  float Wc[2 * HID][WPAD];     // rows 0..63: W1u[:,1:], rows 64..127: W1p[:,2:]
  float cu[HID], cp0[HID], cp1[HID];
  float b1u[HID], b1p[HID], W2u[HID], W2p[HID];
  float cnt_n1[ROWS], cnt01[ROWS], cnt10[ROWS], cnt11[ROWS];
  float partial[NWARP][ROWS];
};

__device__ __forceinline__ float gelu_f(float x) {
  // exact erf-based GELU (matches torch nn.GELU default / jax approximate=False)
  return 0.5f * x * (1.0f + erff(x * 0.7071067811865476f));
}

extern __shared__ __align__(16) float smem_raw[];

__global__ void __launch_bounds__(THREADS) fem_kernel(
    const float* __restrict__ u,   const float* __restrict__ h,
    const float* __restrict__ W1u, const float* __restrict__ b1u,
    const float* __restrict__ W2u, const float* __restrict__ b2u,
    const float* __restrict__ W1p, const float* __restrict__ b1p,
    const float* __restrict__ W2p, const float* __restrict__ b2p,
    float* __restrict__ out)
{
  Smem* s = reinterpret_cast<Smem*>(smem_raw);
  const int tid  = threadIdx.x;
  const int lane = tid & 31;
  const int w    = tid >> 5;
  const int r0   = blockIdx.x * ROWS;

  // ---- load h tile [32 x 128] (coalesced float4) ----
  {
    const float4* h4 = reinterpret_cast<const float4*>(h) + (size_t)r0 * (DIMH / 4);
    for (int i = tid; i < ROWS * (DIMH / 4); i += THREADS) {
      float4 v = h4[i];
      int row = i >> 5, c4 = i & 31;
      *reinterpret_cast<float4*>(&s->hs[row][c4 * 4]) = v;
    }
  }
  // ---- load W1u [64 x 129]: col 0 -> cu, cols 1.. -> Wc[j] ----
  for (int i = tid; i < HID * 129; i += THREADS) {
    int j = i / 129, c = i - j * 129;
    float v = W1u[i];
    if (c == 0) s->cu[j] = v;
    else        s->Wc[j][c - 1] = v;
  }
  // ---- load W1p [64 x 130]: cols 0,1 -> cp0,cp1, cols 2.. -> Wc[64+j] ----
  for (int i = tid; i < HID * 130; i += THREADS) {
    int j = i / 130, c = i - j * 130;
    float v = W1p[i];
    if (c == 0)      s->cp0[j] = v;
    else if (c == 1) s->cp1[j] = v;
    else             s->Wc[HID + j][c - 2] = v;
  }
  if (tid < HID) {
    s->b1u[tid] = b1u[tid];
    s->b1p[tid] = b1p[tid];
    s->W2u[tid] = W2u[tid];
    s->W2p[tid] = W2p[tid];
  }

  // ---- count u bits per row: n1 and consecutive-pair class counts ----
  // warp w handles rows w, w+8, w+16, w+24. lane covers elems [4*lane..4*lane+3]
  // in each half of the 256-wide row (two float4 loads).
  {
    const float4* u4 = reinterpret_cast<const float4*>(u);
    for (int rr = w; rr < ROWS; rr += NWARP) {
      size_t base = (size_t)(r0 + rr) * (DIMU / 4);
      float4 a = u4[base + lane];        // elems 4l .. 4l+3
      float4 b = u4[base + 32 + lane];   // elems 128+4l .. 128+4l+3
      int a0 = a.x > 0.5f, a1 = a.y > 0.5f, a2 = a.z > 0.5f, a3 = a.w > 0.5f;
      int e0 = b.x > 0.5f, e1 = b.y > 0.5f, e2 = b.z > 0.5f, e3 = b.w > 0.5f;
      int n1 = a0 + a1 + a2 + a3 + e0 + e1 + e2 + e3;
      const unsigned F = 0xffffffffu;
      int a0n  = __shfl_down_sync(F, a0, 1);  // next lane's a0
      int e0n  = __shfl_down_sync(F, e0, 1);  // next lane's b0
      int e0l0 = __shfl_sync(F, e0, 0);       // lane0's b0 == element 128
      int c11 = 0, c10 = 0, c01 = 0;
#define ADDP(X, Y) { c11 += (X) & (Y); c10 += (X) & (1 ^ (Y)); c01 += (1 ^ (X)) & (Y); }
      ADDP(a0, a1) ADDP(a1, a2) ADDP(a2, a3)
      int xa = (lane < 31) ? a0n : e0l0;      // pair (4l+3, 4l+4); lane31 -> (127,128)
      ADDP(a3, xa)
      ADDP(e0, e1) ADDP(e1, e2) ADDP(e2, e3)
      if (lane < 31) ADDP(e3, e0n)            // lane31's (255,256) doesn't exist
#undef ADDP
      n1  = __reduce_add_sync(F, n1);
      c11 = __reduce_add_sync(F, c11);
      c10 = __reduce_add_sync(F, c10);
      c01 = __reduce_add_sync(F, c01);
      if (lane == 0) {
        s->cnt_n1[rr] = (float)n1;
        s->cnt11[rr]  = (float)c11;
        s->cnt10[rr]  = (float)c10;
        s->cnt01[rr]  = (float)c01;
      }
    }
  }

  __syncthreads();

  // ---- fused GEMM: lane = row, warp owns 16 j-columns (j = w*16 + jj) ----
  // acc2[jj] holds a packed f32x2 partial sum over even/odd k pairs.
  unsigned long long acc2[16];
#pragma unroll
  for (int jj = 0; jj < 16; jj++) acc2[jj] = 0ull;
  const int jbase = w * 16;
  const float* hrow  = s->hs[lane];
  const float* wbase = s->Wc[jbase];
#pragma unroll 2
  for (int k = 0; k < DIMH; k += 4) {
    ulonglong2 hv = *reinterpret_cast<const ulonglong2*>(hrow + k);   // 4 h values
#pragma unroll
    for (int jj = 0; jj < 16; jj++) {
      ulonglong2 wv = *reinterpret_cast<const ulonglong2*>(wbase + jj * WPAD + k);
      asm("fma.rn.f32x2 %0, %1, %2, %0;" : "+l"(acc2[jj]) : "l"(hv.x), "l"(wv.x));
      asm("fma.rn.f32x2 %0, %1, %2, %0;" : "+l"(acc2[jj]) : "l"(hv.y), "l"(wv.y));
    }
  }

  // ---- epilogue: binary-u collapse to 2 (unary) / 4 (pairwise) gelu variants ----
  float n1  = s->cnt_n1[lane];
  float c01 = s->cnt01[lane];
  float c10 = s->cnt10[lane];
  float c11 = s->cnt11[lane];
  float val;
  if (w < 4) {
    float g0 = 0.f, g1 = 0.f;
#pragma unroll
    for (int jj = 0; jj < 16; jj++) {
      int j = jbase + jj;
      float lo, hi;
      asm("mov.b64 {%0, %1}, %2;" : "=f"(lo), "=f"(hi) : "l"(acc2[jj]));
      float base = lo + hi + s->b1u[j];
      float w2 = s->W2u[j];
      g0 += w2 * gelu_f(base);
      g1 += w2 * gelu_f(base + s->cu[j]);
    }
    val = (256.0f - n1) * g0 + n1 * g1;
  } else {
    float p00 = 0.f, p01 = 0.f, p10 = 0.f, p11 = 0.f;
#pragma unroll
    for (int jj = 0; jj < 16; jj++) {
      int j = jbase - HID + jj;
      float lo, hi;
      asm("mov.b64 {%0, %1}, %2;" : "=f"(lo), "=f"(hi) : "l"(acc2[jj]));
      float base = lo + hi + s->b1p[j];
      float A  = s->cp0[j];   // multiplies u_i
      float Bv = s->cp1[j];   // multiplies u_{i+1}
      float w2 = s->W2p[j];
      p00 += w2 * gelu_f(base);
      p01 += w2 * gelu_f(base + Bv);
      p10 += w2 * gelu_f(base + A);
      p11 += w2 * gelu_f(base + A + Bv);
    }
    float c00 = 255.0f - c01 - c10 - c11;
    val = c00 * p00 + c01 * p01 + c10 * p10 + c11 * p11;
  }
  s->partial[w][lane] = val;
  __syncthreads();

  if (w == 0) {
    float e = 0.f;
#pragma unroll
    for (int ww = 0; ww < NWARP; ww++) e += s->partial[ww][lane];
    e += 256.0f * b2u[0] + 255.0f * b2p[0];
    out[r0 + lane] = e;
  }
}

extern "C" void kernel_launch(void* const* d_in, const int* in_sizes, int n_in,
                              void* d_out, int out_size) {
  const float* u   = (const float*)d_in[0];
  const float* h   = (const float*)d_in[1];
  const float* W1u = (const float*)d_in[2];
  const float* b1u = (const float*)d_in[3];
  const float* W2u = (const float*)d_in[4];
  const float* b2u = (const float*)d_in[5];
  const float* W1p = (const float*)d_in[6];
  const float* b1p = (const float*)d_in[7];
  const float* W2p = (const float*)d_in[8];
  const float* b2p = (const float*)d_in[9];
  float* out = (float*)d_out;

  int B    = in_sizes[1] / DIMH;   // 4096
  int grid = B / ROWS;             // 128 blocks
  size_t smem = sizeof(Smem);      // ~88 KB -> needs opt-in
  cudaFuncSetAttribute(fem_kernel, cudaFuncAttributeMaxDynamicSharedMemorySize, (int)smem);
  fem_kernel<<<grid, THREADS, smem>>>(u, h, W1u, b1u, W2u, b2u, W1p, b1p, W2p, b2p, out);
}

// round 2
// speedup vs baseline: 1.1636x; 1.1636x over previous
#include <cuda_runtime.h>
#include <cstdint>
#include <cstddef>

#define HID     64
#define DIMH    128
#define DIMU    256
#define ROWS    32
#define NWARP   16
#define THREADS 512
#define JPW     8     // j-columns per warp (16 warps x 8 = 128)
#define WPAD    132   // padded row length (floats): conflict-free stride, 16B-aligned

struct Smem {
  float hs[ROWS][WPAD];        // h tile
  float Wc[2 * HID][WPAD];     // rows 0..63: W1u[:,1:], rows 64..127: W1p[:,2:]
  float cu[HID], cp0[HID], cp1[HID];
  float b1u[HID], b1p[HID], W2u[HID], W2p[HID];
  float cnt_n1[ROWS], cnt01[ROWS], cnt10[ROWS], cnt11[ROWS];
  float partial[NWARP][ROWS];
};

__device__ __forceinline__ float gelu_f(float x) {
  // exact erf-based GELU (matches torch nn.GELU default / jax approximate=False)
  return 0.5f * x * (1.0f + erff(x * 0.7071067811865476f));
}

extern __shared__ __align__(16) float smem_raw[];

__global__ void __launch_bounds__(THREADS) fem_kernel(
    const float* __restrict__ u,   const float* __restrict__ h,
    const float* __restrict__ W1u, const float* __restrict__ b1u,
    const float* __restrict__ W2u, const float* __restrict__ b2u,
    const float* __restrict__ W1p, const float* __restrict__ b1p,
    const float* __restrict__ W2p, const float* __restrict__ b2p,
    float* __restrict__ out)
{
  Smem* s = reinterpret_cast<Smem*>(smem_raw);
  const int tid  = threadIdx.x;
  const int lane = tid & 31;
  const int w    = tid >> 5;
  const int r0   = blockIdx.x * ROWS;

  // ---- load h tile [32 x 128] (coalesced float4) ----
  {
    const float4* h4 = reinterpret_cast<const float4*>(h) + (size_t)r0 * (DIMH / 4);
    for (int i = tid; i < ROWS * (DIMH / 4); i += THREADS) {
      float4 v = h4[i];
      int row = i >> 5, c4 = i & 31;
      *reinterpret_cast<float4*>(&s->hs[row][c4 * 4]) = v;
    }
  }
  // ---- load W1u [64 x 129]: col 0 -> cu, cols 1.. -> Wc[j] ----
  for (int i = tid; i < HID * 129; i += THREADS) {
    int j = i / 129, c = i - j * 129;
    float v = W1u[i];
    if (c == 0) s->cu[j] = v;
    else        s->Wc[j][c - 1] = v;
  }
  // ---- load W1p [64 x 130]: cols 0,1 -> cp0,cp1, cols 2.. -> Wc[64+j] ----
  for (int i = tid; i < HID * 130; i += THREADS) {
    int j = i / 130, c = i - j * 130;
    float v = W1p[i];
    if (c == 0)      s->cp0[j] = v;
    else if (c == 1) s->cp1[j] = v;
    else             s->Wc[HID + j][c - 2] = v;
  }
  if (tid < HID) {
    s->b1u[tid] = b1u[tid];
    s->b1p[tid] = b1p[tid];
    s->W2u[tid] = W2u[tid];
    s->W2p[tid] = W2p[tid];
  }

  // ---- count u bits per row: n1 and consecutive-pair class counts ----
  // warp w handles rows w, w+16. lane covers elems [4*lane..4*lane+3]
  // in each half of the 256-wide row (two float4 loads).
  {
    const float4* u4 = reinterpret_cast<const float4*>(u);
    for (int rr = w; rr < ROWS; rr += NWARP) {
      size_t base = (size_t)(r0 + rr) * (DIMU / 4);
      float4 a = u4[base + lane];        // elems 4l .. 4l+3
      float4 b = u4[base + 32 + lane];   // elems 128+4l .. 128+4l+3
      int a0 = a.x > 0.5f, a1 = a.y > 0.5f, a2 = a.z > 0.5f, a3 = a.w > 0.5f;
      int e0 = b.x > 0.5f, e1 = b.y > 0.5f, e2 = b.z > 0.5f, e3 = b.w > 0.5f;
      int n1 = a0 + a1 + a2 + a3 + e0 + e1 + e2 + e3;
      const unsigned F = 0xffffffffu;
      int a0n  = __shfl_down_sync(F, a0, 1);  // next lane's a0
      int e0n  = __shfl_down_sync(F, e0, 1);  // next lane's b0
      int e0l0 = __shfl_sync(F, e0, 0);       // lane0's b0 == element 128
      int c11 = 0, c10 = 0, c01 = 0;
#define ADDP(X, Y) { c11 += (X) & (Y); c10 += (X) & (1 ^ (Y)); c01 += (1 ^ (X)) & (Y); }
      ADDP(a0, a1) ADDP(a1, a2) ADDP(a2, a3)
      int xa = (lane < 31) ? a0n : e0l0;      // pair (4l+3, 4l+4); lane31 -> (127,128)
      ADDP(a3, xa)
      ADDP(e0, e1) ADDP(e1, e2) ADDP(e2, e3)
      if (lane < 31) ADDP(e3, e0n)            // lane31's (255,256) doesn't exist
#undef ADDP
      n1  = __reduce_add_sync(F, n1);
      c11 = __reduce_add_sync(F, c11);
      c10 = __reduce_add_sync(F, c10);
      c01 = __reduce_add_sync(F, c01);
      if (lane == 0) {
        s->cnt_n1[rr] = (float)n1;
        s->cnt11[rr]  = (float)c11;
        s->cnt10[rr]  = (float)c10;
        s->cnt01[rr]  = (float)c01;
      }
    }
  }

  __syncthreads();

  // ---- fused GEMM: lane = row, warp owns JPW=8 j-columns (Wc row jbase+jj) ----
  // acc2[jj] holds a packed f32x2 partial sum over even/odd k pairs.
  unsigned long long acc2[JPW];
#pragma unroll
  for (int jj = 0; jj < JPW; jj++) acc2[jj] = 0ull;
  const int jbase = w * JPW;           // 0..120: rows of Wc
  const float* hrow  = s->hs[lane];
  const float* wbase = s->Wc[jbase];
#pragma unroll 2
  for (int k = 0; k < DIMH; k += 4) {
    ulonglong2 hv = *reinterpret_cast<const ulonglong2*>(hrow + k);   // 4 h values
#pragma unroll
    for (int jj = 0; jj < JPW; jj++) {
      ulonglong2 wv = *reinterpret_cast<const ulonglong2*>(wbase + jj * WPAD + k);
      asm("fma.rn.f32x2 %0, %1, %2, %0;" : "+l"(acc2[jj]) : "l"(hv.x), "l"(wv.x));
      asm("fma.rn.f32x2 %0, %1, %2, %0;" : "+l"(acc2[jj]) : "l"(hv.y), "l"(wv.y));
    }
  }

  // ---- epilogue: binary-u collapse to 2 (unary) / 4 (pairwise) gelu variants ----
  // warps 0..7 cover unary j=0..63; warps 8..15 cover pairwise j=0..63.
  // Sum over warps is linear in the per-warp partial variants, so the
  // count-weighted combination can be applied per-warp and summed.
  float n1  = s->cnt_n1[lane];
  float c01 = s->cnt01[lane];
  float c10 = s->cnt10[lane];
  float c11 = s->cnt11[lane];
  float val;
  if (w < NWARP / 2) {
    float g0 = 0.f, g1 = 0.f;
#pragma unroll
    for (int jj = 0; jj < JPW; jj++) {
      int j = jbase + jj;
      float lo, hi;
      asm("mov.b64 {%0, %1}, %2;" : "=f"(lo), "=f"(hi) : "l"(acc2[jj]));
      float base = lo + hi + s->b1u[j];
      float w2 = s->W2u[j];
      g0 += w2 * gelu_f(base);
      g1 += w2 * gelu_f(base + s->cu[j]);
    }
    val = (256.0f - n1) * g0 + n1 * g1;
  } else {
    float p00 = 0.f, p01 = 0.f, p10 = 0.f, p11 = 0.f;
#pragma unroll
    for (int jj = 0; jj < JPW; jj++) {
      int j = jbase - HID + jj;
      float lo, hi;
      asm("mov.b64 {%0, %1}, %2;" : "=f"(lo), "=f"(hi) : "l"(acc2[jj]));
      float base = lo + hi + s->b1p[j];
      float A  = s->cp0[j];   // multiplies u_i
      float Bv = s->cp1[j];   // multiplies u_{i+1}
      float w2 = s->W2p[j];
      p00 += w2 * gelu_f(base);
      p01 += w2 * gelu_f(base + Bv);
      p10 += w2 * gelu_f(base + A);
      p11 += w2 * gelu_f(base + A + Bv);
    }
    float c00 = 255.0f - c01 - c10 - c11;
    val = c00 * p00 + c01 * p01 + c10 * p10 + c11 * p11;
  }
  s->partial[w][lane] = val;
  __syncthreads();

  if (w == 0) {
    float e = 0.f;
#pragma unroll
    for (int ww = 0; ww < NWARP; ww++) e += s->partial[ww][lane];
    e += 256.0f * b2u[0] + 255.0f * b2p[0];
    out[r0 + lane] = e;
  }
}

extern "C" void kernel_launch(void* const* d_in, const int* in_sizes, int n_in,
                              void* d_out, int out_size) {
  const float* u   = (const float*)d_in[0];
  const float* h   = (const float*)d_in[1];
  const float* W1u = (const float*)d_in[2];
  const float* b1u = (const float*)d_in[3];
  const float* W2u = (const float*)d_in[4];
  const float* b2u = (const float*)d_in[5];
  const float* W1p = (const float*)d_in[6];
  const float* b1p = (const float*)d_in[7];
  const float* W2p = (const float*)d_in[8];
  const float* b2p = (const float*)d_in[9];
  float* out = (float*)d_out;

  int B    = in_sizes[1] / DIMH;   // 4096
  int grid = B / ROWS;             // 128 blocks
  size_t smem = sizeof(Smem);      // ~87 KB -> needs opt-in
  cudaFuncSetAttribute(fem_kernel, cudaFuncAttributeMaxDynamicSharedMemorySize, (int)smem);
  fem_kernel<<<grid, THREADS, smem>>>(u, h, W1u, b1u, W2u, b2u, W1p, b1p, W2p, b2p, out);
}